// round 6
// baseline (speedup 1.0000x reference)
#include <cuda_runtime.h>
#include <math.h>
#include <stdint.h>

// Problem constants
#define Bx 4
#define Lx 4096
#define Hx 8
#define Ex 64
#define Mx 64
#define Cx 512            // H*E
#define KP 2304           // padded folded K (>= 2049), = 18*128
#define NSPLIT 18
#define KCHUNK 128

typedef unsigned long long u64;

// Static device scratch (no allocations allowed)
__device__ float g_bc[Mx * KP];                 // cos(2*pi*m*l/L), [m][l], pads 0
__device__ float g_bs[Mx * KP];                 // -sin(...),       [m][l], pads 0
__device__ float g_bcT[KP * Mx];                // transposed [l][m]
__device__ float g_bsT[KP * Mx];
__device__ float g_part[8 * NSPLIT * Mx * Cx];  // split-K partials
__device__ float g_X[8 * Mx * Cx];              // X[bp][m][c], bp = b*2 + (0:Re,1:Im)
__device__ float g_res[Bx * Cx * 2 * Mx];       // res[b][c][0..63 ReS | 64..127 ImS]

// packed f32x2 helpers
__device__ __forceinline__ void fma2(u64& d, u64 a, u64 b) {
    asm("fma.rn.f32x2 %0, %1, %2, %0;" : "+l"(d) : "l"(a), "l"(b));
}
__device__ __forceinline__ float2 unpk(u64 v) {
    float2 r;
    asm("mov.b64 {%0, %1}, %2;" : "=f"(r.x), "=f"(r.y) : "l"(v));
    return r;
}
__device__ __forceinline__ u64 dup(float v) {
    u64 r;
    asm("mov.b64 %0, {%1, %1};" : "=l"(r) : "f"(v));
    return r;
}
__device__ __forceinline__ uint32_t s2u(const void* p) {
    return (uint32_t)__cvta_generic_to_shared(p);
}
__device__ __forceinline__ void cpa16(uint32_t dst, const void* src) {
    asm volatile("cp.async.cg.shared.global [%0], [%1], 16;" :: "r"(dst), "l"(src));
}
__device__ __forceinline__ void cpa_commit() {
    asm volatile("cp.async.commit_group;");
}
template <int N>
__device__ __forceinline__ void cpa_wait() {
    asm volatile("cp.async.wait_group %0;" :: "n"(N));
}

// ---------------------------------------------------------------------------
// K0: build all basis tables.
// ---------------------------------------------------------------------------
__global__ void k_basisAll() {
    int id = blockIdx.x * blockDim.x + threadIdx.x;
    if (id >= Mx * KP) return;
    int m = id / KP, l = id - m * KP;
    float c = 0.f, s = 0.f;
    if (l <= 2048) {
        int r = (m * l) & (Lx - 1);
        sincospif((float)r / 2048.0f, &s, &c);
    }
    g_bc[id] = c;
    g_bs[id] = -s;
    g_bcT[(size_t)l * Mx + m] = c;
    g_bsT[(size_t)l * Mx + m] = -s;
}

// ---------------------------------------------------------------------------
// K1: forward GEMM, split-K, fold fused, Re+Im fused, FFMA2,
// ping-pong smem double buffer + cp.async A tables, 1 sync per iter.
// Block: 64 m x 128 c, 256 threads, per thread 8m x 4c, 2 blocks/SM.
// ---------------------------------------------------------------------------
__global__ void __launch_bounds__(256, 2) k_fwd(const float* __restrict__ q) {
    __shared__ float2 Bsum[2][8][64];
    __shared__ float2 Bdif[2][8][64];
    __shared__ float  Acs[2][8][64];
    __shared__ float  Ass[2][8][64];

    const int t = threadIdx.x;
    const int ct = blockIdx.x;      // 0..3
    const int split = blockIdx.y;   // 0..17
    const int b = blockIdx.z;       // 0..3
    const int c0 = ct * 128;
    const int k0 = split * KCHUNK;
    const int tx = t & 31, ty = t >> 5;    // tx: 4c, ty: 8m (uniform/warp)
    const int bkk = t >> 5, bcg = t & 31;  // B loader
    const int akk = t >> 4, amg = t & 15;  // A loader (t<128)
    const bool al = (t < 128);
    const float* qb = q + (size_t)b * Lx * Cx;
    const uint32_t acs_a = s2u(&Acs[0][0][0]);
    const uint32_t ass_a = s2u(&Ass[0][0][0]);

    u64 accRe[8][2], accIm[8][2];
#pragma unroll
    for (int r = 0; r < 8; r++) {
        accRe[r][0] = accRe[r][1] = 0ull;
        accIm[r][0] = accIm[r][1] = 0ull;
    }

    float4 pa, pmm;

#define LDQ(lval)                                                              \
    {   int l_ = (lval);                                                       \
        pa = make_float4(0.f, 0.f, 0.f, 0.f); pmm = pa;                        \
        if (l_ <= 2048) {                                                      \
            pa = *(const float4*)(qb + (size_t)l_ * Cx + c0 + bcg * 4);        \
            if (l_ == 0 || l_ == 2048) {                                       \
                pa.x *= 0.5f; pa.y *= 0.5f; pa.z *= 0.5f; pa.w *= 0.5f;        \
                pmm = pa;                                                      \
            } else {                                                           \
                pmm = *(const float4*)(qb + (size_t)(Lx - l_) * Cx + c0 + bcg * 4); \
            }                                                                  \
        }                                                                      \
    }

#define STSB(st_)                                                              \
    {   float4 vs = make_float4(pa.x + pmm.x, pa.y + pmm.y, pa.z + pmm.z, pa.w + pmm.w); \
        float4 vd = make_float4(pa.x - pmm.x, pa.y - pmm.y, pa.z - pmm.z, pa.w - pmm.w); \
        *(float4*)&Bsum[st_][bkk][bcg * 2] = vs;                               \
        *(float4*)&Bdif[st_][bkk][bcg * 2] = vd;                               \
    }

#define CPA_A(lbase, st_)                                                      \
    if (al) {                                                                  \
        cpa16(acs_a + (uint32_t)(((st_) * 512 + akk * 64 + amg * 4) * 4),      \
              g_bcT + (size_t)((lbase) + akk) * Mx + amg * 4);                 \
        cpa16(ass_a + (uint32_t)(((st_) * 512 + akk * 64 + amg * 4) * 4),      \
              g_bsT + (size_t)((lbase) + akk) * Mx + amg * 4);                 \
    }

    // prologue
    LDQ(k0 + bkk);
    CPA_A(k0, 0);
    cpa_commit();                 // g0 = A(k0)
    STSB(0);                      // stalls on q LDG once
    LDQ(k0 + 8 + bkk);
    CPA_A(k0 + 8, 1);
    cpa_commit();                 // g1 = A(k0+8)
    cpa_wait<1>();                // A(k0) done
    __syncthreads();

#pragma unroll 1
    for (int i = 0; i < KCHUNK / 8; i++) {
        const int st = i & 1;
        const int kc = k0 + i * 8;
        // compute stage st
#pragma unroll
        for (int kk = 0; kk < 8; kk++) {
            float4 bq = *(const float4*)&Bsum[st][kk][tx * 2];
            float4 dq = *(const float4*)&Bdif[st][kk][tx * 2];
            u64 b0 = *(u64*)&bq.x, b1 = *(u64*)&bq.z;
            u64 d0 = *(u64*)&dq.x, d1 = *(u64*)&dq.z;
            float4 ac0 = *(const float4*)&Acs[st][kk][ty * 8];
            float4 ac1 = *(const float4*)&Acs[st][kk][ty * 8 + 4];
            float4 as0 = *(const float4*)&Ass[st][kk][ty * 8];
            float4 as1 = *(const float4*)&Ass[st][kk][ty * 8 + 4];
            float acv[8] = {ac0.x, ac0.y, ac0.z, ac0.w, ac1.x, ac1.y, ac1.z, ac1.w};
            float asv[8] = {as0.x, as0.y, as0.z, as0.w, as1.x, as1.y, as1.z, as1.w};
#pragma unroll
            for (int r = 0; r < 8; r++) {
                u64 a2 = dup(acv[r]);
                u64 s2 = dup(asv[r]);
                fma2(accRe[r][0], a2, b0);
                fma2(accRe[r][1], a2, b1);
                fma2(accIm[r][0], s2, d0);
                fma2(accIm[r][1], s2, d1);
            }
        }
        if (i < KCHUNK / 8 - 1) {
            STSB(st ^ 1);                          // B(kc+8) regs -> other stage
            if (i < KCHUNK / 8 - 2) {
                LDQ(kc + 16 + bkk);                // q for iter i+2
                CPA_A(kc + 16, st);                // A for iter i+2 into freed stage
            }
            cpa_commit();
            if (i >= KCHUNK / 8 - 3) { cpa_wait<0>(); } else { cpa_wait<1>(); }
            __syncthreads();
        }
    }
#undef LDQ
#undef STSB
#undef CPA_A

    float* oRe = g_part + ((size_t)(b * 2 + 0) * NSPLIT + split) * (Mx * Cx);
    float* oIm = g_part + ((size_t)(b * 2 + 1) * NSPLIT + split) * (Mx * Cx);
#pragma unroll
    for (int r = 0; r < 8; r++) {
        int m = ty * 8 + r;
        float2 lo = unpk(accRe[r][0]), hi = unpk(accRe[r][1]);
        *(float4*)(oRe + (size_t)m * Cx + c0 + tx * 4) =
            make_float4(lo.x, lo.y, hi.x, hi.y);
        float2 lo2 = unpk(accIm[r][0]), hi2 = unpk(accIm[r][1]);
        *(float4*)(oIm + (size_t)m * Cx + c0 + tx * 4) =
            make_float4(lo2.x, lo2.y, hi2.x, hi2.y);
    }
}

// ---------------------------------------------------------------------------
// K2: reduce split-K partials -> g_X (float4)
// ---------------------------------------------------------------------------
__global__ void k_reduce() {
    int o4 = blockIdx.x * blockDim.x + threadIdx.x;
    int bp = o4 >> 13;
    int inner = o4 & 8191;
    const float4* p = (const float4*)g_part + (size_t)bp * NSPLIT * 8192 + inner;
    float4 s = make_float4(0.f, 0.f, 0.f, 0.f);
#pragma unroll
    for (int sp = 0; sp < NSPLIT; sp++) {
        float4 v = p[(size_t)sp * 8192];
        s.x += v.x; s.y += v.y; s.z += v.z; s.w += v.w;
    }
    ((float4*)g_X)[o4] = s;
}

// ---------------------------------------------------------------------------
// K3: head mixing + irfft scaling. Block = (e-quad, o, b); 256 threads (m,eq).
// ---------------------------------------------------------------------------
__global__ void k_mix(const float* __restrict__ wr, const float* __restrict__ wi) {
    __shared__ float sX[2][8][4][64];   // [re/im][i][eq][m]
    int t = threadIdx.x;
    int eq4 = blockIdx.x;
    int o = blockIdx.y;
    int b = blockIdx.z;
    int e0 = eq4 * 4;

#pragma unroll
    for (int s = 0; s < 4; s++) {
        int idx = t + 256 * s;
        int tab = idx >> 9;
        int rem = idx & 511;
        int m = rem >> 3, i = rem & 7;
        float4 v = *(const float4*)(g_X + ((size_t)(b * 2 + tab) * Mx + m) * Cx + i * 64 + e0);
        sX[tab][i][0][m] = v.x;
        sX[tab][i][1][m] = v.y;
        sX[tab][i][2][m] = v.z;
        sX[tab][i][3][m] = v.w;
    }
    __syncthreads();

    int m = t & 63, eqi = t >> 6;
    int e = e0 + eqi;
    float re = 0.f, im = 0.f;
#pragma unroll
    for (int i = 0; i < Hx; i++) {
        float xr = sX[0][i][eqi][m];
        float xi = sX[1][i][eqi][m];
        size_t wIdx = (((size_t)i * Hx + o) * Ex + e) * Mx + m;
        float wre = wr[wIdx], wim = wi[wIdx];
        re += xr * wre - xi * wim;
        im += xr * wim + xi * wre;
    }
    float scR = (m == 0) ? (1.0f / Lx) : (2.0f / Lx);
    float* r = g_res + ((size_t)(b * Cx) + o * Ex + e) * 128;
    r[m] = re * scR;
    r[64 + m] = (m == 0) ? 0.f : im * (2.0f / Lx);
}

// ---------------------------------------------------------------------------
// K4: inverse synthesis. f32x2 lanes = ROW PAIRS; 16 rows x 2 l per thread.
//   E[l] = sum_m ReS*bc[m][l];  O[l] = sum_m ImS*bs[m][l]
//   out[l] = E+O (l<2048); out[L-l] = E-O (l=1..2047)
// Block: 128 rows x 64 l, 256 threads, 2 blocks/SM, ~90 live regs (no spill).
// Dynamic smem: saT[128 j][128 row] + sbc/sbs[16][64] single-stage (cp.async).
// ---------------------------------------------------------------------------
#define SMEM_INV (128 * 128 * 4 + 2 * 16 * 64 * 4)   // 64KB + 8KB

__global__ void __launch_bounds__(256, 2) k_inv(float* __restrict__ out) {
    extern __shared__ float sm[];
    float* saT = sm;                 // [j=0..127][row 0..127], stride 128
    float* sbc = sm + 128 * 128;     // [16][64]
    float* sbs = sbc + 16 * 64;

    const int t = threadIdx.x;
    const int ltile = blockIdx.x;            // 0..31 (64 l each)
    const int rowBase = blockIdx.y * 128;    // 0..15
    const int l0b = ltile * 64;
    const uint32_t sbc_a = s2u(sbc), sbs_a = s2u(sbs);
    const int mr = t >> 4, j4 = t & 15;      // basis loader: 16 m x 16 float4

#define CPA_B(ch_)                                                             \
    {   cpa16(sbc_a + (uint32_t)((mr * 64 + j4 * 4) * 4),                      \
              g_bc + (size_t)((ch_) * 16 + mr) * KP + l0b + j4 * 4);           \
        cpa16(sbs_a + (uint32_t)((mr * 64 + j4 * 4) * 4),                      \
              g_bs + (size_t)((ch_) * 16 + mr) * KP + l0b + j4 * 4);           \
        cpa_commit();                                                          \
    }

    CPA_B(0);

    // fill transposed res tile: 128 rows x 128 j
#pragma unroll
    for (int s = 0; s < 16; s++) {
        int i4 = t + 256 * s;
        int row = i4 & 127, jj = i4 >> 7;    // jj 0..31
        float4 v = *(const float4*)(g_res + (size_t)(rowBase + row) * 128 + jj * 4);
        saT[(jj * 4 + 0) * 128 + row] = v.x;
        saT[(jj * 4 + 1) * 128 + row] = v.y;
        saT[(jj * 4 + 2) * 128 + row] = v.z;
        saT[(jj * 4 + 3) * 128 + row] = v.w;
    }

    const int tx = t & 31, ty = t >> 5;      // tx: 2 l, ty: 16-row group (uniform)
    const int l0 = l0b + tx * 2;

    u64 E[8][2], O[8][2];
#pragma unroll
    for (int p = 0; p < 8; p++) {
        E[p][0] = E[p][1] = 0ull;
        O[p][0] = O[p][1] = 0ull;
    }

#pragma unroll 1
    for (int ch = 0; ch < 4; ch++) {
        cpa_wait<0>();
        __syncthreads();         // basis ch visible; (ch=0) saT done
#pragma unroll
        for (int mm = 0; mm < 16; mm++) {
            int m = ch * 16 + mm;
            float2 c2 = *(const float2*)&sbc[mm * 64 + tx * 2];
            float2 s2 = *(const float2*)&sbs[mm * 64 + tx * 2];
            u64 cd0 = dup(c2.x), cd1 = dup(c2.y);
            u64 sd0 = dup(s2.x), sd1 = dup(s2.y);
            const float* pre = &saT[(size_t)m * 128 + ty * 16];
            const float* pim = &saT[(size_t)(64 + m) * 128 + ty * 16];
#pragma unroll
            for (int h = 0; h < 4; h++) {
                float4 qa = *(const float4*)(pre + h * 4);   // uniform
                float4 qi = *(const float4*)(pim + h * 4);
                u64 a0 = *(u64*)&qa.x, a1 = *(u64*)&qa.z;
                u64 b0 = *(u64*)&qi.x, b1 = *(u64*)&qi.z;
                fma2(E[2 * h][0], a0, cd0);     fma2(E[2 * h][1], a0, cd1);
                fma2(E[2 * h + 1][0], a1, cd0); fma2(E[2 * h + 1][1], a1, cd1);
                fma2(O[2 * h][0], b0, sd0);     fma2(O[2 * h][1], b0, sd1);
                fma2(O[2 * h + 1][0], b1, sd0); fma2(O[2 * h + 1][1], b1, sd1);
            }
        }
        if (ch < 3) {
            __syncthreads();     // all warps done with sbc/sbs
            CPA_B(ch + 1);
        }
    }
#undef CPA_B

    // epilogue: lanes of E/O pairs are rows (2p, 2p+1); u index is l0+u
#pragma unroll
    for (int p = 0; p < 8; p++) {
        int r0 = rowBase + ty * 16 + 2 * p;
        int r1 = r0 + 1;
        float2 e0 = unpk(E[p][0]), e1 = unpk(E[p][1]);
        float2 o0 = unpk(O[p][0]), o1 = unpk(O[p][1]);
        *(float2*)(out + (size_t)r0 * Lx + l0) = make_float2(e0.x + o0.x, e1.x + o1.x);
        *(float2*)(out + (size_t)r1 * Lx + l0) = make_float2(e0.y + o0.y, e1.y + o1.y);
        if (l0 > 0) {
            out[(size_t)r0 * Lx + (Lx - l0)]     = e0.x - o0.x;
            out[(size_t)r0 * Lx + (Lx - l0 - 1)] = e1.x - o1.x;
            out[(size_t)r1 * Lx + (Lx - l0)]     = e0.y - o0.y;
            out[(size_t)r1 * Lx + (Lx - l0 - 1)] = e1.y - o1.y;
        } else {
            out[(size_t)r0 * Lx + (Lx - 1)] = e1.x - o1.x;
            out[(size_t)r1 * Lx + (Lx - 1)] = e1.y - o1.y;
        }
    }
}

// ---------------------------------------------------------------------------
// K5: l = 2048 edge. bc[m][2048] = (-1)^m, bs term = 0.
// ---------------------------------------------------------------------------
__global__ void k_edge(float* __restrict__ out) {
    int row = blockIdx.x * blockDim.x + threadIdx.x;
    const float* r = g_res + (size_t)row * 128;
    float s = 0.f;
#pragma unroll
    for (int m = 0; m < 64; m += 2) { s += r[m]; s -= r[m + 1]; }
    out[(size_t)row * Lx + 2048] = s;
}

// ---------------------------------------------------------------------------
extern "C" void kernel_launch(void* const* d_in, const int* in_sizes, int n_in,
                              void* d_out, int out_size) {
    const float* q  = (const float*)d_in[0];
    const float* wr = (const float*)d_in[3];
    const float* wi = (const float*)d_in[4];
    float* out = (float*)d_out;

    cudaFuncSetAttribute(k_inv, cudaFuncAttributeMaxDynamicSharedMemorySize, SMEM_INV);

    k_basisAll<<<(Mx * KP + 255) / 256, 256>>>();
    {
        dim3 g(4, NSPLIT, Bx);   // 288 blocks
        k_fwd<<<g, 256>>>(q);
    }
    k_reduce<<<256, 256>>>();
    {
        dim3 g(16, 8, 4);
        k_mix<<<g, 256>>>(wr, wi);   // <- 4th launch: profiled
    }
    {
        dim3 g(32, 16);          // 512 blocks
        k_inv<<<g, 256, SMEM_INV>>>(out);
    }
    k_edge<<<8, 256>>>(out);
}

// round 7
// speedup vs baseline: 1.1920x; 1.1920x over previous
#include <cuda_runtime.h>
#include <math.h>
#include <stdint.h>

// Problem constants
#define Bx 4
#define Lx 4096
#define Hx 8
#define Ex 64
#define Mx 64
#define Cx 512            // H*E
#define KP 2304           // padded folded K (>= 2049), = 18*128
#define NSPLIT 18
#define KCHUNK 128

typedef unsigned long long u64;

// Static device scratch (no allocations allowed)
__device__ float g_part[8 * NSPLIT * Mx * Cx];  // split-K partials
__device__ float g_X[8 * Mx * Cx];              // X[bp][m][c], bp = b*2 + (0:Re,1:Im)
__device__ float g_resT2[16 * 64 * 128 * 2];    // [rb][m][row][{reS,imS}]

// packed f32x2 helpers
__device__ __forceinline__ void fma2(u64& d, u64 a, u64 b) {
    asm("fma.rn.f32x2 %0, %1, %2, %0;" : "+l"(d) : "l"(a), "l"(b));
}
__device__ __forceinline__ float2 unpk(u64 v) {
    float2 r;
    asm("mov.b64 {%0, %1}, %2;" : "=f"(r.x), "=f"(r.y) : "l"(v));
    return r;
}
__device__ __forceinline__ u64 dup(float v) {
    u64 r;
    asm("mov.b64 %0, {%1, %1};" : "=l"(r) : "f"(v));
    return r;
}

// ---------------------------------------------------------------------------
// K1: forward GEMM, split-K, fold fused, Re+Im fused, FFMA2, basis generated
// in-kernel via sincospif (no tables, no table LDGs).
//   Re[m][c] = sum_l cos(2pi m l/L) * (q[l]+q[L-l])[c]   (l=0,2048 half-weight)
//   Im[m][c] = sum_l -sin(2pi m l/L) * (q[l]-q[L-l])[c]
// Block: 64 m x 128 c, 256 threads, per thread 8m x 4c, 2 blocks/SM.
// ---------------------------------------------------------------------------
__global__ void __launch_bounds__(256, 2) k_fwd(const float* __restrict__ q) {
    __shared__ float2 Bsum[8][64];   // [kk][c/2]
    __shared__ float2 Bdif[8][64];
    __shared__ float  Acs[8][64];    // [kk][m]  cos
    __shared__ float  Ass[8][64];    // [kk][m]  -sin

    const int t = threadIdx.x;
    const int ct = blockIdx.x;      // 0..3  (c-tile of 128)
    const int split = blockIdx.y;   // 0..17
    const int b = blockIdx.z;       // 0..3
    const int c0 = ct * 128;
    const int k0 = split * KCHUNK;
    const int tx = t & 31, ty = t >> 5;    // tx: 4c, ty: 8m (uniform/warp)
    const int bkk = t >> 5, bcg = t & 31;  // B loader: 8kk x 32 float4
    const int gm = t & 63;                 // A gen: m index
    const int gk = t >> 6;                 // A gen: kk (0..3), second id kk+4
    const float* qb = q + (size_t)b * Lx * Cx;

    u64 accRe[8][2], accIm[8][2];
#pragma unroll
    for (int r = 0; r < 8; r++) {
        accRe[r][0] = accRe[r][1] = 0ull;
        accIm[r][0] = accIm[r][1] = 0ull;
    }

    float4 pa, pmm;

#define LDQ(lval)                                                              \
    {   int l_ = (lval);                                                       \
        pa = make_float4(0.f, 0.f, 0.f, 0.f); pmm = pa;                        \
        if (l_ <= 2048) {                                                      \
            pa = *(const float4*)(qb + (size_t)l_ * Cx + c0 + bcg * 4);        \
            if (l_ == 0 || l_ == 2048) {                                       \
                pa.x *= 0.5f; pa.y *= 0.5f; pa.z *= 0.5f; pa.w *= 0.5f;        \
                pmm = pa;                                                      \
            } else {                                                           \
                pmm = *(const float4*)(qb + (size_t)(Lx - l_) * Cx + c0 + bcg * 4); \
            }                                                                  \
        }                                                                      \
    }

#define GENA(kk_, lval)                                                        \
    {   int l_ = (lval);                                                       \
        float cs = 0.f, sn = 0.f;                                              \
        if (l_ <= 2048) {                                                      \
            int r_ = (gm * l_) & (Lx - 1);                                     \
            sincospif((float)r_ / 2048.0f, &sn, &cs);                          \
        }                                                                      \
        Acs[kk_][gm] = cs;                                                     \
        Ass[kk_][gm] = -sn;                                                    \
    }

    // prologue: prefetch chunk k0
    LDQ(k0 + bkk);

    for (int kc = k0; kc < k0 + KCHUNK; kc += 8) {
        // store prefetched B (fold fused) + generate A for this chunk
        {
            float4 vs = make_float4(pa.x + pmm.x, pa.y + pmm.y, pa.z + pmm.z, pa.w + pmm.w);
            float4 vd = make_float4(pa.x - pmm.x, pa.y - pmm.y, pa.z - pmm.z, pa.w - pmm.w);
            *(float4*)&Bsum[bkk][bcg * 2] = vs;
            *(float4*)&Bdif[bkk][bcg * 2] = vd;
            GENA(gk, kc + gk);
            GENA(gk + 4, kc + gk + 4);
        }
        __syncthreads();
        // prefetch next chunk (LDG latency hidden by compute below)
        if (kc + 8 < k0 + KCHUNK) { LDQ(kc + 8 + bkk); }
        // compute 8 kk
#pragma unroll
        for (int kk = 0; kk < 8; kk++) {
            float4 bq = *(const float4*)&Bsum[kk][tx * 2];   // b0|b1
            float4 dq = *(const float4*)&Bdif[kk][tx * 2];   // d0|d1
            u64 b0 = *(u64*)&bq.x, b1 = *(u64*)&bq.z;
            u64 d0 = *(u64*)&dq.x, d1 = *(u64*)&dq.z;
            float4 ac0 = *(const float4*)&Acs[kk][ty * 8];   // uniform
            float4 ac1 = *(const float4*)&Acs[kk][ty * 8 + 4];
            float4 as0 = *(const float4*)&Ass[kk][ty * 8];
            float4 as1 = *(const float4*)&Ass[kk][ty * 8 + 4];
            float acv[8] = {ac0.x, ac0.y, ac0.z, ac0.w, ac1.x, ac1.y, ac1.z, ac1.w};
            float asv[8] = {as0.x, as0.y, as0.z, as0.w, as1.x, as1.y, as1.z, as1.w};
#pragma unroll
            for (int r = 0; r < 8; r++) {
                u64 a2 = dup(acv[r]);
                u64 s2 = dup(asv[r]);
                fma2(accRe[r][0], a2, b0);
                fma2(accRe[r][1], a2, b1);
                fma2(accIm[r][0], s2, d0);
                fma2(accIm[r][1], s2, d1);
            }
        }
        __syncthreads();
    }
#undef LDQ
#undef GENA

    float* oRe = g_part + ((size_t)(b * 2 + 0) * NSPLIT + split) * (Mx * Cx);
    float* oIm = g_part + ((size_t)(b * 2 + 1) * NSPLIT + split) * (Mx * Cx);
#pragma unroll
    for (int r = 0; r < 8; r++) {
        int m = ty * 8 + r;
        float2 lo = unpk(accRe[r][0]), hi = unpk(accRe[r][1]);
        *(float4*)(oRe + (size_t)m * Cx + c0 + tx * 4) =
            make_float4(lo.x, lo.y, hi.x, hi.y);
        float2 lo2 = unpk(accIm[r][0]), hi2 = unpk(accIm[r][1]);
        *(float4*)(oIm + (size_t)m * Cx + c0 + tx * 4) =
            make_float4(lo2.x, lo2.y, hi2.x, hi2.y);
    }
}

// ---------------------------------------------------------------------------
// K2: reduce split-K partials -> g_X (float4)
// ---------------------------------------------------------------------------
__global__ void k_reduce() {
    int o4 = blockIdx.x * blockDim.x + threadIdx.x;
    int bp = o4 >> 13;
    int inner = o4 & 8191;
    const float4* p = (const float4*)g_part + (size_t)bp * NSPLIT * 8192 + inner;
    float4 s = make_float4(0.f, 0.f, 0.f, 0.f);
#pragma unroll
    for (int sp = 0; sp < NSPLIT; sp++) {
        float4 v = p[(size_t)sp * 8192];
        s.x += v.x; s.y += v.y; s.z += v.z; s.w += v.w;
    }
    ((float4*)g_X)[o4] = s;
}

// ---------------------------------------------------------------------------
// K3: head mixing + irfft scaling + transposed (re,im)-interleaved output
// + fused l=2048 edge column.
//   res[b,o,e,m] = sum_i X[b,i,e,m] * (wr + i*wi)[i,o,e,m]
// Writes g_resT2[rb][m][row][{reS,imS}], row = (b*512+o*64+e) & 127.
// Edge: out[row][2048] = sum_m reS[m] * (-1)^m.
// ---------------------------------------------------------------------------
__global__ void k_mix(const float* __restrict__ wr, const float* __restrict__ wi,
                      float* __restrict__ out) {
    __shared__ float sX[2][8][4][64];   // [re/im][i][eq][m]
    __shared__ float sred[4][64];
    int t = threadIdx.x;
    int eq4 = blockIdx.x;   // 0..15
    int o = blockIdx.y;     // 0..7
    int b = blockIdx.z;     // 0..3
    int e0 = eq4 * 4;

#pragma unroll
    for (int s = 0; s < 4; s++) {
        int idx = t + 256 * s;
        int tab = idx >> 9;
        int rem = idx & 511;
        int m = rem >> 3, i = rem & 7;
        float4 v = *(const float4*)(g_X + ((size_t)(b * 2 + tab) * Mx + m) * Cx + i * 64 + e0);
        sX[tab][i][0][m] = v.x;
        sX[tab][i][1][m] = v.y;
        sX[tab][i][2][m] = v.z;
        sX[tab][i][3][m] = v.w;
    }
    __syncthreads();

    int m = t & 63, eqi = t >> 6;
    int e = e0 + eqi;
    float re = 0.f, im = 0.f;
#pragma unroll
    for (int i = 0; i < Hx; i++) {
        float xr = sX[0][i][eqi][m];
        float xi = sX[1][i][eqi][m];
        size_t wIdx = (((size_t)i * Hx + o) * Ex + e) * Mx + m;
        float wre = wr[wIdx], wim = wi[wIdx];
        re += xr * wre - xi * wim;
        im += xr * wim + xi * wre;
    }
    float scR = (m == 0) ? (1.0f / Lx) : (2.0f / Lx);
    float reS = re * scR;
    float imS = (m == 0) ? 0.f : im * (2.0f / Lx);

    int rowg = b * 512 + o * 64 + e;
    int rb = rowg >> 7, ri = rowg & 127;
    *(float2*)(g_resT2 + (((size_t)rb * 64 + m) * 128 + ri) * 2) =
        make_float2(reS, imS);

    // edge reduction: sum_m reS * (-1)^m per row
    sred[eqi][m] = (m & 1) ? -reS : reS;
    __syncthreads();
    if (t < 4) {
        float s = 0.f;
#pragma unroll
        for (int mm = 0; mm < 64; mm++) s += sred[t][mm];
        int rowe = b * 512 + o * 64 + e0 + t;
        out[(size_t)rowe * Lx + 2048] = s;
    }
}

// ---------------------------------------------------------------------------
// K4: inverse synthesis. f32x2 lanes = (E, O) components!
//   acc(E,O)[row][l] += (reS,imS)[m,row] * (cos, -sin)[m,l]
//   out[row][l] = E+O (l<2048); out[row][L-l] = E-O (l=1..2047)
// a-operands: uniform LDG.128 from g_resT2 (L1-resident 64KB slice).
// basis: sincospif-generated into smem as (c,-s) pairs.
// Block: 64 rows x 128 l, 256 threads, per thread 8 rows x 4 l (2+2 split).
// ---------------------------------------------------------------------------
__global__ void __launch_bounds__(256, 2) k_inv(float* __restrict__ out) {
    __shared__ float sb[16][128][2];   // [mm][l][{c,-s}] 16KB

    const int t = threadIdx.x;
    const int ltile = blockIdx.x;            // 0..15 (128 l each)
    const int by = blockIdx.y;               // 0..31 (64 rows each)
    const int l0b = ltile * 128;
    const int rb = by >> 1;
    const int rowL = (by & 1) * 64 + (t >> 5) * 8;   // local row base in rb
    const int tx = t & 31;
    const int lA = l0b + tx * 2;             // l values: lA, lA+1, lB, lB+1
    const int lB = lA + 64;

    u64 acc[8][4];                            // [row][l-slot], lanes = (E,O)
#pragma unroll
    for (int r = 0; r < 8; r++)
#pragma unroll
        for (int u = 0; u < 4; u++) acc[r][u] = 0ull;

#pragma unroll 1
    for (int ch = 0; ch < 4; ch++) {
        __syncthreads();
        // generate 16-mode basis chunk: 2048 (c,s) pairs, 8 per thread
#pragma unroll
        for (int s = 0; s < 8; s++) {
            int id = t + 256 * s;
            int mm = id >> 7, ll = id & 127;
            int m_ = ch * 16 + mm;
            int r_ = (m_ * (l0b + ll)) & (Lx - 1);
            float sn, cs;
            sincospif((float)r_ / 2048.0f, &sn, &cs);
            *(float2*)&sb[mm][ll][0] = make_float2(cs, -sn);
        }
        __syncthreads();
#pragma unroll
        for (int mm = 0; mm < 16; mm++) {
            int m = ch * 16 + mm;
            // a: 8 rows of (re,im), uniform per warp, via L1
            const float4* ap = (const float4*)(g_resT2 +
                (((size_t)rb * 64 + m) * 128 + rowL) * 2);
            float4 a0 = __ldg(ap);
            float4 a1 = __ldg(ap + 1);
            float4 a2 = __ldg(ap + 2);
            float4 a3 = __ldg(ap + 3);
            u64 av[8] = {*(u64*)&a0.x, *(u64*)&a0.z, *(u64*)&a1.x, *(u64*)&a1.z,
                         *(u64*)&a2.x, *(u64*)&a2.z, *(u64*)&a3.x, *(u64*)&a3.z};
            // basis: (c,-s) pairs for lA,lA+1 and lB,lB+1 (contiguous LDS.128)
            float4 cA = *(const float4*)&sb[mm][tx * 2][0];
            float4 cB = *(const float4*)&sb[mm][64 + tx * 2][0];
            u64 bv[4] = {*(u64*)&cA.x, *(u64*)&cA.z, *(u64*)&cB.x, *(u64*)&cB.z};
#pragma unroll
            for (int r = 0; r < 8; r++) {
#pragma unroll
                for (int u = 0; u < 4; u++) fma2(acc[r][u], av[r], bv[u]);
            }
        }
    }

    // epilogue: lane0 = E, lane1 = O
#pragma unroll
    for (int r = 0; r < 8; r++) {
        int row = rb * 128 + rowL + r;
        float2 p0 = unpk(acc[r][0]);   // lA
        float2 p1 = unpk(acc[r][1]);   // lA+1
        float2 p2 = unpk(acc[r][2]);   // lB
        float2 p3 = unpk(acc[r][3]);   // lB+1
        *(float2*)(out + (size_t)row * Lx + lA) =
            make_float2(p0.x + p0.y, p1.x + p1.y);
        *(float2*)(out + (size_t)row * Lx + lB) =
            make_float2(p2.x + p2.y, p3.x + p3.y);
        if (lA > 0) {
            out[(size_t)row * Lx + (Lx - lA)]     = p0.x - p0.y;
        } else {
            // lA == 0: no mirror for l=0
        }
        out[(size_t)row * Lx + (Lx - lA - 1)] = p1.x - p1.y;
        out[(size_t)row * Lx + (Lx - lB)]     = p2.x - p2.y;
        out[(size_t)row * Lx + (Lx - lB - 1)] = p3.x - p3.y;
    }
}

// ---------------------------------------------------------------------------
extern "C" void kernel_launch(void* const* d_in, const int* in_sizes, int n_in,
                              void* d_out, int out_size) {
    const float* q  = (const float*)d_in[0];
    const float* wr = (const float*)d_in[3];
    const float* wi = (const float*)d_in[4];
    float* out = (float*)d_out;

    {
        dim3 g(4, NSPLIT, Bx);   // 288 blocks
        k_fwd<<<g, 256>>>(q);
    }
    k_reduce<<<256, 256>>>();
    {
        dim3 g(16, 8, 4);
        k_mix<<<g, 256>>>(wr, wi, out);
    }
    {
        dim3 g(16, 32);          // 512 blocks
        k_inv<<<g, 256>>>(out);  // <- 4th launch: profiled
    }
}